// round 2
// baseline (speedup 1.0000x reference)
#include <cuda_runtime.h>
#include <stdint.h>

// Problem constants (fixed shapes from reference: B=8, K=4, N=131072)
#define T_TOTAL   4194304      // B*K*N
#define TILE      4096         // elements per block
#define NBLK      1024         // T_TOTAL / TILE
#define NT        256          // threads per block
#define NEG_IDLE_F (-100000000.0f)
#define NEG_FILL_F (-1000.0f)

// Scratch (device globals — no allocation allowed in kernel_launch)
__device__ int g_sum_s[NBLK];
__device__ int g_sum_a[NBLK];
__device__ int g_off_s[NBLK];
__device__ int g_off_a[NBLK];

// ---------------------------------------------------------------------------
// Kernel 1: per-tile popcount of both masks.
// Masks are 4-byte elements (int32 0/1 or float32 0.0/1.0); nonzero == true.
// Each block: TILE=4096 elems = 4 iterations of 256 threads x uint4.
// ---------------------------------------------------------------------------
__global__ __launch_bounds__(NT) void k_count(const uint32_t* __restrict__ ms,
                                              const uint32_t* __restrict__ ma) {
    int blk = blockIdx.x, tid = threadIdx.x;
    const uint4* s4 = reinterpret_cast<const uint4*>(ms + (size_t)blk * TILE);
    const uint4* a4 = reinterpret_cast<const uint4*>(ma + (size_t)blk * TILE);
    int cs = 0, ca = 0;
    #pragma unroll
    for (int j = 0; j < 4; j++) {
        uint4 s = s4[j * NT + tid];
        uint4 a = a4[j * NT + tid];
        cs += (s.x != 0) + (s.y != 0) + (s.z != 0) + (s.w != 0);
        ca += (a.x != 0) + (a.y != 0) + (a.z != 0) + (a.w != 0);
    }
    #pragma unroll
    for (int o = 16; o > 0; o >>= 1) {
        cs += __shfl_xor_sync(0xffffffffu, cs, o);
        ca += __shfl_xor_sync(0xffffffffu, ca, o);
    }
    __shared__ int sh[16];
    int w = tid >> 5;
    if ((tid & 31) == 0) { sh[w] = cs; sh[8 + w] = ca; }
    __syncthreads();
    if (tid == 0) {
        int ts = 0, ta = 0;
        #pragma unroll
        for (int i = 0; i < 8; i++) { ts += sh[i]; ta += sh[8 + i]; }
        g_sum_s[blk] = ts;
        g_sum_a[blk] = ta;
    }
}

// ---------------------------------------------------------------------------
// Kernel 2: exclusive scan of the 1024 tile sums (one block, 1024 threads)
// ---------------------------------------------------------------------------
__global__ __launch_bounds__(1024) void k_scan() {
    int tid = threadIdx.x, lane = tid & 31, w = tid >> 5;
    int vs = g_sum_s[tid], va = g_sum_a[tid];
    int is = vs, ia = va;
    #pragma unroll
    for (int o = 1; o < 32; o <<= 1) {
        int t = __shfl_up_sync(0xffffffffu, is, o); if (lane >= o) is += t;
        t     = __shfl_up_sync(0xffffffffu, ia, o); if (lane >= o) ia += t;
    }
    __shared__ int ws[32], wa[32];
    if (lane == 31) { ws[w] = is; wa[w] = ia; }
    __syncthreads();
    if (w == 0) {
        int ts = ws[lane], ta = wa[lane];
        int js = ts, ja = ta;
        #pragma unroll
        for (int o = 1; o < 32; o <<= 1) {
            int t = __shfl_up_sync(0xffffffffu, js, o); if (lane >= o) js += t;
            t     = __shfl_up_sync(0xffffffffu, ja, o); if (lane >= o) ja += t;
        }
        ws[lane] = js - ts;   // exclusive warp offsets
        wa[lane] = ja - ta;
    }
    __syncthreads();
    g_off_s[tid] = ws[w] + is - vs;   // global exclusive prefix per tile
    g_off_a[tid] = wa[w] + ia - va;
}

// ---------------------------------------------------------------------------
// Kernel 3: fused expand/gather/write.
// Each thread handles 4 consecutive elements per iteration (4 iterations).
// Surface+air counts packed into one int for a single warp scan (carry-safe:
// per-tile counts <= 4096 < 2^16).
// ---------------------------------------------------------------------------
__global__ __launch_bounds__(NT) void k_main(
    const uint32_t* __restrict__ ms, const uint32_t* __restrict__ ma,
    const float* __restrict__ rgb, const float* __restrict__ ls,
    const float* __restrict__ la,  const float* __restrict__ idle_st,
    float* __restrict__ rgb_out, float* __restrict__ ls_out,
    float* __restrict__ la_out) {

    int blk = blockIdx.x, tid = threadIdx.x;
    int lane = tid & 31, w = tid >> 5;

    // tile lives entirely inside one (b,k) row: N = 32 tiles of 4096
    float idle   = idle_st[blk >> 5];
    float scale  = 1.0f - idle;
    float negadd = idle * NEG_IDLE_F;

    int run_s = g_off_s[blk];
    int run_a = g_off_a[blk];

    __shared__ int shp[2][8];

    #pragma unroll
    for (int j = 0; j < 4; j++) {
        int e0 = blk * TILE + j * (NT * 4) + tid * 4;
        uint4 m4s = *reinterpret_cast<const uint4*>(ms + e0);
        uint4 m4a = *reinterpret_cast<const uint4*>(ma + e0);

        unsigned mb_s[4] = { m4s.x != 0, m4s.y != 0, m4s.z != 0, m4s.w != 0 };
        unsigned mb_a[4] = { m4a.x != 0, m4a.y != 0, m4a.z != 0, m4a.w != 0 };

        int cs = (int)(mb_s[0] + mb_s[1] + mb_s[2] + mb_s[3]);
        int ca = (int)(mb_a[0] + mb_a[1] + mb_a[2] + mb_a[3]);
        int p  = cs | (ca << 16);

        // inclusive warp scan of packed counts
        int ip = p;
        #pragma unroll
        for (int o = 1; o < 32; o <<= 1) {
            int t = __shfl_up_sync(0xffffffffu, ip, o);
            if (lane >= o) ip += t;
        }
        if (lane == 31) shp[j & 1][w] = ip;   // warp total (packed)
        __syncthreads();

        int woff = 0, tot = 0;
        #pragma unroll
        for (int k = 0; k < 8; k++) {
            int v = shp[j & 1][k];
            if (k < w) woff += v;
            tot += v;
        }
        int ep    = ip - p + woff;          // exclusive packed prefix in this 1024-chunk
        int idx_s = run_s + (ep & 0xffff);
        int idx_a = run_a + (ep >> 16);
        run_s += (tot & 0xffff);
        run_a += (tot >> 16);

        float outl_s[4], outl_a[4], ro[12];

        #pragma unroll
        for (int q = 0; q < 4; q++) {
            if (mb_s[q]) {
                outl_s[q] = __ldg(ls + idx_s) * scale + negadd;
                const float* rp = rgb + (size_t)idx_s * 3;
                ro[q * 3 + 0] = rp[0] * scale;
                ro[q * 3 + 1] = rp[1] * scale;
                ro[q * 3 + 2] = rp[2] * scale;
                idx_s++;
            } else {
                outl_s[q] = NEG_FILL_F;
                ro[q * 3 + 0] = 0.0f; ro[q * 3 + 1] = 0.0f; ro[q * 3 + 2] = 0.0f;
            }
            if (mb_a[q]) {
                outl_a[q] = __ldg(la + idx_a) * scale + negadd;
                idx_a++;
            } else {
                outl_a[q] = NEG_FILL_F;
            }
        }

        // Coalesced 16B stores; e0 is a multiple of 4 -> all float4 aligned.
        *reinterpret_cast<float4*>(ls_out + e0) =
            make_float4(outl_s[0], outl_s[1], outl_s[2], outl_s[3]);
        *reinterpret_cast<float4*>(la_out + e0) =
            make_float4(outl_a[0], outl_a[1], outl_a[2], outl_a[3]);
        float4* rout = reinterpret_cast<float4*>(rgb_out + (size_t)e0 * 3);
        rout[0] = make_float4(ro[0], ro[1],  ro[2],  ro[3]);
        rout[1] = make_float4(ro[4], ro[5],  ro[6],  ro[7]);
        rout[2] = make_float4(ro[8], ro[9],  ro[10], ro[11]);
    }
}

// ---------------------------------------------------------------------------
// Launch (graph-capturable: 3 kernel launches, no allocs, no syncs)
// Input order per reference setup_inputs():
//   0 rgb (T,3) f32, 1 logits_surface (T,1) f32, 2 logits_air (T,1) f32,
//   3 mask_surface (B,K,N) int32/f32 0-or-1, 4 mask_air same, 5 idle (B,K) f32
// Output: concat of rgb_out (T*3), logits_surface_out (T), logits_air_out (T)
// ---------------------------------------------------------------------------
extern "C" void kernel_launch(void* const* d_in, const int* in_sizes, int n_in,
                              void* d_out, int out_size) {
    const float*    rgb  = (const float*)d_in[0];
    const float*    ls   = (const float*)d_in[1];
    const float*    la   = (const float*)d_in[2];
    const uint32_t* msf  = (const uint32_t*)d_in[3];
    const uint32_t* maf  = (const uint32_t*)d_in[4];
    const float*    idle = (const float*)d_in[5];

    float* out     = (float*)d_out;
    float* rgb_out = out;
    float* ls_out  = out + (size_t)T_TOTAL * 3;
    float* la_out  = ls_out + T_TOTAL;

    k_count<<<NBLK, NT>>>(msf, maf);
    k_scan<<<1, 1024>>>();
    k_main<<<NBLK, NT>>>(msf, maf, rgb, ls, la, idle, rgb_out, ls_out, la_out);
}